// round 9
// baseline (speedup 1.0000x reference)
#include <cuda_runtime.h>
#include <math.h>
#include <stdint.h>

#define M_ROWS 512
#define K_COMP 8
#define B_PTS  4096
#define PHI_DIM 120
#define Z_COLS 80
#define LOG2PI_F 1.8378770664093453f
#define LOG2E_F  1.4426950408889634f

#define NBLK   296          // 148 SMs x 2 CTAs x 256 threads
#define NTILE  256          // 4096 pts / 16 per mma tile
#define MB_N   64           // m-blocks of 8 m
#define PC_N   32           // point-chunks of 8 tiles (one per warp)
#define NTICK  (MB_N * PC_N)

// Scratch (device globals — no allocation allowed)
__device__ float g_Af[NTILE][2][2][32][4];   // A (feature) frags: [tile][s][h][lane][reg]
__device__ float g_Bf[M_ROWS][4][32][2];     // B (coef) frags: [m][s*2+h][lane][reg]
__device__ float g_zT[72][M_ROWS];           // z cols 0..71, column-major
__device__ float g_respT2[K_COMP][M_ROWS][NTILE];  // per-tile resp partials
__device__ float g_respF[K_COMP][M_ROWS];    // reduced resp
__device__ unsigned g_ticket, g_bar[3], g_done;

__device__ __forceinline__ float ex2f(float x) {
    float r; asm("ex2.approx.f32 %0, %1;" : "=f"(r) : "f"(x)); return r;
}
__device__ __forceinline__ float rcpf(float x) {
    float r; asm("rcp.approx.f32 %0, %1;" : "=f"(r) : "f"(x)); return r;
}
__device__ __forceinline__ float tf32_rn(float v) {
    uint32_t u; asm("cvt.rna.tf32.f32 %0, %1;" : "=r"(u) : "f"(v));
    return __uint_as_float(u);
}
__device__ __forceinline__ void mma_tf32(float& d0, float& d1, float& d2, float& d3,
                                         uint32_t a0, uint32_t a1, uint32_t a2, uint32_t a3,
                                         uint32_t b0, uint32_t b1) {
    asm volatile("mma.sync.aligned.m16n8k8.row.col.f32.tf32.tf32.f32 "
                 "{%0,%1,%2,%3}, {%4,%5,%6,%7}, {%8,%9}, {%0,%1,%2,%3};"
                 : "+f"(d0), "+f"(d1), "+f"(d2), "+f"(d3)
                 : "r"(a0), "r"(a1), "r"(a2), "r"(a3), "r"(b0), "r"(b1));
}

__device__ __forceinline__ void grid_barrier(unsigned* ctr) {
    __syncthreads();
    if (threadIdx.x == 0) {
        __threadfence();
        atomicAdd(ctr, 1u);
        volatile unsigned* p = ctr;
        while (*p < NBLK) __nanosleep(64);
    }
    __syncthreads();
    __threadfence();
}

// ---------------------------------------------------------------------------
__global__ void __launch_bounds__(256, 2) gmm_all(const float* __restrict__ phi,
                                                  const float4* __restrict__ X,
                                                  float* __restrict__ out) {
    const int tid = threadIdx.x;
    const unsigned lane = tid & 31;
    const unsigned wid = tid >> 5;

    __shared__ float sB[8 * 256];     // 8 m x 256 floats of B frags
    __shared__ unsigned s_item;

    // ================= PHASE 0: prep (coef tasks 0..4095, feature 4096..8191)
    {
        int gid = blockIdx.x * 256 + tid;
        if (gid < M_ROWS * K_COMP) {
            // ---- coefficient task for (m,k) ----
            const int m = gid >> 3, k = gid & 7;
            const float* pm = phi + m * PHI_DIM;

            float mx = -INFINITY;
            #pragma unroll
            for (int j = 0; j < K_COMP; j++) mx = fmaxf(mx, pm[j]);
            float s = 0.f;
            #pragma unroll
            for (int j = 0; j < K_COMP; j++) s += __expf(pm[j] - mx);
            float pik = __expf(pm[k] - mx) / s;

            float mu0 = pm[8 + k * 4 + 0];
            float mu1 = pm[8 + k * 4 + 1];
            float mu2 = pm[8 + k * 4 + 2];
            float mu3 = pm[8 + k * 4 + 3];

            const float* lv = pm + 40 + k * 10;
            float L00 = lv[0], L10 = lv[1], L11 = lv[2], L20 = lv[3], L21 = lv[4];
            float L22 = lv[5], L30 = lv[6], L31 = lv[7], L32 = lv[8], L33 = lv[9];

            float G00 = 1.0f / L00, G11 = 1.0f / L11, G22 = 1.0f / L22, G33 = 1.0f / L33;
            float G10 = -L10 * G00 * G11;
            float G21 = -L21 * G11 * G22;
            float G20 = -(L20 * G00 + L21 * G10) * G22;
            float G32 = -L32 * G22 * G33;
            float G31 = -(L31 * G11 + L32 * G21) * G33;
            float G30 = -(L30 * G00 + L31 * G10 + L32 * G20) * G33;

            const float sc = sqrtf(0.5f * LOG2E_F);
            float A00 = sc * G00, A10 = sc * G10, A11 = sc * G11;
            float A20 = sc * G20, A21 = sc * G21, A22 = sc * G22;
            float A30 = sc * G30, A31 = sc * G31, A32 = sc * G32, A33 = sc * G33;

            float B0 = -(A00 * mu0);
            float B1 = -(A10 * mu0 + A11 * mu1);
            float B2 = -(A20 * mu0 + A21 * mu1 + A22 * mu2);
            float B3 = -(A30 * mu0 + A31 * mu1 + A32 * mu2 + A33 * mu3);

            float log_det = 2.0f * (__logf(fmaxf(fabsf(L00), 1e-8f)) +
                                    __logf(fmaxf(fabsf(L11), 1e-8f)) +
                                    __logf(fmaxf(fabsf(L22), 1e-8f)) +
                                    __logf(fmaxf(fabsf(L33), 1e-8f)));
            float ckv = __logf(fmaxf(pik, 1e-8f)) - 0.5f * (4.0f * LOG2PI_F + log_det);
            float ck2 = ckv * LOG2E_F;

            // quadratic-form coefficients: q - ck2 = c . f(x)
            float S00 = A00*A00 + A10*A10 + A20*A20 + A30*A30;
            float S01 = A10*A11 + A20*A21 + A30*A31;
            float S02 = A20*A22 + A30*A32;
            float S03 = A30*A33;
            float S11 = A11*A11 + A21*A21 + A31*A31;
            float S12 = A21*A22 + A31*A32;
            float S13 = A31*A33;
            float S22 = A22*A22 + A32*A32;
            float S23 = A32*A33;
            float S33 = A33*A33;
            float w0 = A00*B0 + A10*B1 + A20*B2 + A30*B3;
            float w1 = A11*B1 + A21*B2 + A31*B3;
            float w2 = A22*B2 + A32*B3;
            float w3 = A33*B3;
            float cc = B0*B0 + B1*B1 + B2*B2 + B3*B3 - ck2;

            float c[16] = {S00, S11, S22, S33,
                           2.f*S01, 2.f*S02, 2.f*S03, 2.f*S12, 2.f*S13, 2.f*S23,
                           2.f*w0, 2.f*w1, 2.f*w2, 2.f*w3, cc, 0.f};

            #pragma unroll
            for (int ss = 0; ss < 2; ss++) {
                #pragma unroll
                for (int t = 0; t < 4; t++) {
                    int L = k * 4 + t;
                    float ca = c[8 * ss + t];
                    float cb = c[8 * ss + t + 4];
                    float cah = tf32_rn(ca), cal = tf32_rn(ca - cah);
                    float cbh = tf32_rn(cb), cbl = tf32_rn(cb - cbh);
                    g_Bf[m][ss * 2 + 0][L][0] = cah;
                    g_Bf[m][ss * 2 + 1][L][0] = cal;
                    g_Bf[m][ss * 2 + 0][L][1] = cbh;
                    g_Bf[m][ss * 2 + 1][L][1] = cbl;
                }
            }

            g_zT[k * 4 + 0][m] = mu0;
            g_zT[k * 4 + 1][m] = mu1;
            g_zT[k * 4 + 2][m] = mu2;
            g_zT[k * 4 + 3][m] = mu3;
            g_zT[32 + k * 4 + 0][m] = __logf(fmaxf(fabsf(L00), 1e-6f));
            g_zT[32 + k * 4 + 1][m] = __logf(fmaxf(fabsf(L11), 1e-6f));
            g_zT[32 + k * 4 + 2][m] = __logf(fmaxf(fabsf(L22), 1e-6f));
            g_zT[32 + k * 4 + 3][m] = __logf(fmaxf(fabsf(L33), 1e-6f));
            g_zT[64 + k][m] = pik;
        } else if (gid < M_ROWS * K_COMP + B_PTS) {
            // ---- feature task for point p ----
            const int p = gid - M_ROWS * K_COMP;
            float4 xv = X[p];
            float f[16] = {xv.x*xv.x, xv.y*xv.y, xv.z*xv.z, xv.w*xv.w,
                           xv.x*xv.y, xv.x*xv.z, xv.x*xv.w,
                           xv.y*xv.z, xv.y*xv.w, xv.z*xv.w,
                           xv.x, xv.y, xv.z, xv.w, 1.0f, 0.0f};
            const int T = p >> 4;
            const int row = p & 15;
            const int gg = row & 7;
            const bool up = row < 8;
            const int rA = up ? 0 : 1;
            const int rB = up ? 2 : 3;
            #pragma unroll
            for (int ss = 0; ss < 2; ss++) {
                #pragma unroll
                for (int t = 0; t < 4; t++) {
                    int L = gg * 4 + t;
                    float fa = f[8 * ss + t];
                    float fb = f[8 * ss + t + 4];
                    float fah = tf32_rn(fa), fal = tf32_rn(fa - fah);
                    float fbh = tf32_rn(fb), fbl = tf32_rn(fb - fbh);
                    g_Af[T][ss][0][L][rA] = fah;
                    g_Af[T][ss][1][L][rA] = fal;
                    g_Af[T][ss][0][L][rB] = fbh;
                    g_Af[T][ss][1][L][rB] = fbl;
                }
            }
        }
    }

    grid_barrier(&g_bar[0]);

    // ================= PHASE 1: tensor-core logits + fused softmax ==========
    for (;;) {
        if (tid == 0) s_item = atomicAdd(&g_ticket, 1u);
        __syncthreads();
        const unsigned item = s_item;
        if (item >= NTICK) break;
        const int MB = item >> 5;          // m-block (8 m)
        const int PC = item & 31;          // point-chunk (8 tiles)
        const int mbase = MB * 8;
        const int T = PC * 8 + wid;        // this warp's tile

        // stage B frags for 8 m into smem (2048 floats)
        {
            const float4* src = (const float4*)&g_Bf[mbase][0][0][0];
            float4* dst = (float4*)sB;
            dst[tid] = src[tid];
            dst[tid + 256] = src[tid + 256];
        }
        __syncthreads();

        // load A frags (hi/lo x 2 ksteps)
        const uint4* ap = (const uint4*)&g_Af[T][0][0][0][0];
        uint4 a0 = ap[0 * 32 + lane];   // s=0 hi
        uint4 a1 = ap[1 * 32 + lane];   // s=0 lo
        uint4 a2 = ap[2 * 32 + lane];   // s=1 hi
        uint4 a3 = ap[3 * 32 + lane];   // s=1 lo

        #pragma unroll 2
        for (int mm = 0; mm < 8; mm++) {
            const float2* bp = (const float2*)&sB[mm * 256];
            float2 bf0 = bp[0 * 32 + lane];   // s=0 hi
            float2 bf1 = bp[1 * 32 + lane];   // s=0 lo
            float2 bf2 = bp[2 * 32 + lane];   // s=1 hi
            float2 bf3 = bp[3 * 32 + lane];   // s=1 lo
            uint32_t b0x = __float_as_uint(bf0.x), b0y = __float_as_uint(bf0.y);
            uint32_t b1x = __float_as_uint(bf1.x), b1y = __float_as_uint(bf1.y);
            uint32_t b2x = __float_as_uint(bf2.x), b2y = __float_as_uint(bf2.y);
            uint32_t b3x = __float_as_uint(bf3.x), b3y = __float_as_uint(bf3.y);

            float d0 = 0.f, d1 = 0.f, d2 = 0.f, d3 = 0.f;
            // 3xtf32: hi*hi + lo*hi + hi*lo, both ksteps
            mma_tf32(d0, d1, d2, d3, a0.x, a0.y, a0.z, a0.w, b0x, b0y);
            mma_tf32(d0, d1, d2, d3, a1.x, a1.y, a1.z, a1.w, b0x, b0y);
            mma_tf32(d0, d1, d2, d3, a0.x, a0.y, a0.z, a0.w, b1x, b1y);
            mma_tf32(d0, d1, d2, d3, a2.x, a2.y, a2.z, a2.w, b2x, b2y);
            mma_tf32(d0, d1, d2, d3, a3.x, a3.y, a3.z, a3.w, b2x, b2y);
            mma_tf32(d0, d1, d2, d3, a2.x, a2.y, a2.z, a2.w, b3x, b3y);

            // d = q - ck2 for: (pt g, k 2t), (pt g, 2t+1), (pt g+8, 2t), (pt g+8, 2t+1)
            // softmax over k (min-shift): k spreads across in-lane pair + t lanes
            float v = fminf(d0, d1);
            float w = fminf(d2, d3);
            v = fminf(v, __shfl_xor_sync(0xffffffffu, v, 1));
            v = fminf(v, __shfl_xor_sync(0xffffffffu, v, 2));
            w = fminf(w, __shfl_xor_sync(0xffffffffu, w, 1));
            w = fminf(w, __shfl_xor_sync(0xffffffffu, w, 2));
            float e0 = ex2f(v - d0);
            float e1 = ex2f(v - d1);
            float e2 = ex2f(w - d2);
            float e3 = ex2f(w - d3);
            float sv = e0 + e1;
            sv += __shfl_xor_sync(0xffffffffu, sv, 1);
            sv += __shfl_xor_sync(0xffffffffu, sv, 2);
            float sw = e2 + e3;
            sw += __shfl_xor_sync(0xffffffffu, sw, 1);
            sw += __shfl_xor_sync(0xffffffffu, sw, 2);
            float iv = rcpf(sv);
            float iw = rcpf(sw);
            float r0 = __fmaf_rn(e0, iv, e2 * iw);   // k=2t, pts g & g+8
            float r1 = __fmaf_rn(e1, iv, e3 * iw);   // k=2t+1
            // sum over the 8 pt-groups (g)
            r0 += __shfl_xor_sync(0xffffffffu, r0, 4);
            r0 += __shfl_xor_sync(0xffffffffu, r0, 8);
            r0 += __shfl_xor_sync(0xffffffffu, r0, 16);
            r1 += __shfl_xor_sync(0xffffffffu, r1, 4);
            r1 += __shfl_xor_sync(0xffffffffu, r1, 8);
            r1 += __shfl_xor_sync(0xffffffffu, r1, 16);
            if (lane < 4) {
                g_respT2[2 * lane + 0][mbase + mm][T] = r0;
                g_respT2[2 * lane + 1][mbase + mm][T] = r1;
            }
        }
        __syncthreads();   // protect sB before next ticket
    }

    grid_barrier(&g_bar[1]);

    // ================= PHASE 1.5: reduce per-tile partials ===================
    {
        int gid = blockIdx.x * 256 + tid;
        if (gid < K_COMP * M_ROWS) {
            const int k = gid >> 9, m = gid & 511;
            const float4* rp = (const float4*)&g_respT2[k][m][0];
            float s0 = 0.f, s1 = 0.f, s2 = 0.f, s3 = 0.f;
            #pragma unroll 8
            for (int j = 0; j < NTILE / 4; j++) {
                float4 vv = rp[j];
                s0 += vv.x; s1 += vv.y; s2 += vv.z; s3 += vv.w;
            }
            g_respF[k][m] = ((s0 + s1) + (s2 + s3)) * (1.0f / (float)B_PTS);
        }
    }

    grid_barrier(&g_bar[2]);

    // ================= PHASE 2: standardization (blocks 0..79) ===============
    if (blockIdx.x < Z_COLS) {
        const int c = blockIdx.x;
        float v[2];
        if (c < 72) {
            const float* col = g_zT[c];
            #pragma unroll
            for (int j = 0; j < 2; j++) v[j] = col[tid + 256 * j];
        } else {
            const float* col = g_respF[c - 72];
            #pragma unroll
            for (int j = 0; j < 2; j++) v[j] = col[tid + 256 * j];
        }

        __shared__ float nsh[8];
        __shared__ float n_mean, n_rstd;

        float s = v[0] + v[1];
        s += __shfl_down_sync(0xffffffffu, s, 16);
        s += __shfl_down_sync(0xffffffffu, s, 8);
        s += __shfl_down_sync(0xffffffffu, s, 4);
        s += __shfl_down_sync(0xffffffffu, s, 2);
        s += __shfl_down_sync(0xffffffffu, s, 1);
        if (lane == 0) nsh[wid] = s;
        __syncthreads();
        if (tid == 0) {
            float t = ((nsh[0] + nsh[1]) + (nsh[2] + nsh[3])) +
                      ((nsh[4] + nsh[5]) + (nsh[6] + nsh[7]));
            n_mean = t * (1.0f / (float)M_ROWS);
        }
        __syncthreads();
        float mean = n_mean;

        float qsum = 0.f;
        #pragma unroll
        for (int j = 0; j < 2; j++) {
            v[j] -= mean;
            qsum = __fmaf_rn(v[j], v[j], qsum);
        }
        qsum += __shfl_down_sync(0xffffffffu, qsum, 16);
        qsum += __shfl_down_sync(0xffffffffu, qsum, 8);
        qsum += __shfl_down_sync(0xffffffffu, qsum, 4);
        qsum += __shfl_down_sync(0xffffffffu, qsum, 2);
        qsum += __shfl_down_sync(0xffffffffu, qsum, 1);
        __syncthreads();
        if (lane == 0) nsh[wid] = qsum;
        __syncthreads();
        if (tid == 0) {
            float t = ((nsh[0] + nsh[1]) + (nsh[2] + nsh[3])) +
                      ((nsh[4] + nsh[5]) + (nsh[6] + nsh[7]));
            float var = t * (1.0f / (float)(M_ROWS - 1));
            n_rstd = 1.0f / fmaxf(sqrtf(var), 1e-6f);
        }
        __syncthreads();
        float rstd = n_rstd;
        #pragma unroll
        for (int j = 0; j < 2; j++) {
            int r = tid + 256 * j;
            out[r * Z_COLS + c] = v[j] * rstd;
        }
    }

    // ============== counter reset (state -> 0 for graph replay) ==============
    __syncthreads();
    if (tid == 0) {
        __threadfence();
        unsigned d = atomicAdd(&g_done, 1u);
        if (d == NBLK - 1) {
            g_ticket = 0u;
            g_bar[0] = 0u;
            g_bar[1] = 0u;
            g_bar[2] = 0u;
            g_done = 0u;
            __threadfence();
        }
    }
}

// ---------------------------------------------------------------------------
extern "C" void kernel_launch(void* const* d_in, const int* in_sizes, int n_in,
                              void* d_out, int out_size) {
    const float* phi = (const float*)d_in[0];
    const float4* X = (const float4*)d_in[1];
    float* out = (float*)d_out;

    gmm_all<<<NBLK, 256>>>(phi, X, out);
}

// round 11
// speedup vs baseline: 1.3200x; 1.3200x over previous
#include <cuda_runtime.h>
#include <math.h>
#include <stdint.h>

#define M_ROWS 512
#define K_COMP 8
#define B_PTS  4096
#define PHI_DIM 120
#define Z_COLS 80
#define LOG2PI_F 1.8378770664093453f
#define LOG2E_F  1.4426950408889634f

#define NBLK   296          // 148 SMs x 2 CTAs x 256 threads
#define NTILE  256          // 4096 pts / 16 per mma tile
#define CH_N   16           // point-chunks of 256 points (16 tiles) per m
#define NTICK  (CH_N * M_ROWS)   // 8192 warp tickets

// Scratch (device globals — no allocation allowed)
__device__ float g_Af[NTILE][2][2][32][4];   // A (feature) frags: [tile][s][h][lane][reg]
__device__ float g_Bf[M_ROWS][4][32][2];     // B (coef) frags: [m][s*2+h][lane][reg]
__device__ float g_zT[72][M_ROWS];           // z cols 0..71, column-major
__device__ float g_respC[CH_N][K_COMP][M_ROWS];  // per-chunk resp partials
__device__ float g_respF[K_COMP][M_ROWS];    // reduced resp
__device__ unsigned g_ticket, g_bar[3], g_done;

__device__ __forceinline__ float ex2f(float x) {
    float r; asm("ex2.approx.f32 %0, %1;" : "=f"(r) : "f"(x)); return r;
}
__device__ __forceinline__ float rcpf(float x) {
    float r; asm("rcp.approx.f32 %0, %1;" : "=f"(r) : "f"(x)); return r;
}
__device__ __forceinline__ float tf32_rn(float v) {
    uint32_t u; asm("cvt.rna.tf32.f32 %0, %1;" : "=r"(u) : "f"(v));
    return __uint_as_float(u);
}
__device__ __forceinline__ void mma_tf32(float& d0, float& d1, float& d2, float& d3,
                                         uint32_t a0, uint32_t a1, uint32_t a2, uint32_t a3,
                                         uint32_t b0, uint32_t b1) {
    asm volatile("mma.sync.aligned.m16n8k8.row.col.f32.tf32.tf32.f32 "
                 "{%0,%1,%2,%3}, {%4,%5,%6,%7}, {%8,%9}, {%0,%1,%2,%3};"
                 : "+f"(d0), "+f"(d1), "+f"(d2), "+f"(d3)
                 : "r"(a0), "r"(a1), "r"(a2), "r"(a3), "r"(b0), "r"(b1));
}

__device__ __forceinline__ void grid_barrier(unsigned* ctr) {
    __syncthreads();
    if (threadIdx.x == 0) {
        __threadfence();
        atomicAdd(ctr, 1u);
        volatile unsigned* p = ctr;
        while (*p < NBLK) __nanosleep(64);
    }
    __syncthreads();
    __threadfence();
}

// ---------------------------------------------------------------------------
__global__ void __launch_bounds__(256, 2) gmm_all(const float* __restrict__ phi,
                                                  const float4* __restrict__ X,
                                                  float* __restrict__ out) {
    const int tid = threadIdx.x;
    const unsigned lane = tid & 31;
    const unsigned wid = tid >> 5;

    // per-warp D staging: 2 tiles x 16 rows x stride-12 (conflict-free LDS.128)
    __shared__ __align__(16) float sD[8][2][16][12];

    // ================= PHASE 0: prep (coef tasks 0..4095, feature 4096..8191)
    {
        int gid = blockIdx.x * 256 + tid;
        if (gid < M_ROWS * K_COMP) {
            const int m = gid >> 3, k = gid & 7;
            const float* pm = phi + m * PHI_DIM;

            float mx = -INFINITY;
            #pragma unroll
            for (int j = 0; j < K_COMP; j++) mx = fmaxf(mx, pm[j]);
            float s = 0.f;
            #pragma unroll
            for (int j = 0; j < K_COMP; j++) s += __expf(pm[j] - mx);
            float pik = __expf(pm[k] - mx) / s;

            float mu0 = pm[8 + k * 4 + 0];
            float mu1 = pm[8 + k * 4 + 1];
            float mu2 = pm[8 + k * 4 + 2];
            float mu3 = pm[8 + k * 4 + 3];

            const float* lv = pm + 40 + k * 10;
            float L00 = lv[0], L10 = lv[1], L11 = lv[2], L20 = lv[3], L21 = lv[4];
            float L22 = lv[5], L30 = lv[6], L31 = lv[7], L32 = lv[8], L33 = lv[9];

            float G00 = 1.0f / L00, G11 = 1.0f / L11, G22 = 1.0f / L22, G33 = 1.0f / L33;
            float G10 = -L10 * G00 * G11;
            float G21 = -L21 * G11 * G22;
            float G20 = -(L20 * G00 + L21 * G10) * G22;
            float G32 = -L32 * G22 * G33;
            float G31 = -(L31 * G11 + L32 * G21) * G33;
            float G30 = -(L30 * G00 + L31 * G10 + L32 * G20) * G33;

            const float sc = sqrtf(0.5f * LOG2E_F);
            float A00 = sc * G00, A10 = sc * G10, A11 = sc * G11;
            float A20 = sc * G20, A21 = sc * G21, A22 = sc * G22;
            float A30 = sc * G30, A31 = sc * G31, A32 = sc * G32, A33 = sc * G33;

            float B0 = -(A00 * mu0);
            float B1 = -(A10 * mu0 + A11 * mu1);
            float B2 = -(A20 * mu0 + A21 * mu1 + A22 * mu2);
            float B3 = -(A30 * mu0 + A31 * mu1 + A32 * mu2 + A33 * mu3);

            float log_det = 2.0f * (__logf(fmaxf(fabsf(L00), 1e-8f)) +
                                    __logf(fmaxf(fabsf(L11), 1e-8f)) +
                                    __logf(fmaxf(fabsf(L22), 1e-8f)) +
                                    __logf(fmaxf(fabsf(L33), 1e-8f)));
            float ckv = __logf(fmaxf(pik, 1e-8f)) - 0.5f * (4.0f * LOG2PI_F + log_det);
            float ck2 = ckv * LOG2E_F;

            float S00 = A00*A00 + A10*A10 + A20*A20 + A30*A30;
            float S01 = A10*A11 + A20*A21 + A30*A31;
            float S02 = A20*A22 + A30*A32;
            float S03 = A30*A33;
            float S11 = A11*A11 + A21*A21 + A31*A31;
            float S12 = A21*A22 + A31*A32;
            float S13 = A31*A33;
            float S22 = A22*A22 + A32*A32;
            float S23 = A32*A33;
            float S33 = A33*A33;
            float w0 = A00*B0 + A10*B1 + A20*B2 + A30*B3;
            float w1 = A11*B1 + A21*B2 + A31*B3;
            float w2 = A22*B2 + A32*B3;
            float w3 = A33*B3;
            float cc = B0*B0 + B1*B1 + B2*B2 + B3*B3 - ck2;

            float c[16] = {S00, S11, S22, S33,
                           2.f*S01, 2.f*S02, 2.f*S03, 2.f*S12, 2.f*S13, 2.f*S23,
                           2.f*w0, 2.f*w1, 2.f*w2, 2.f*w3, cc, 0.f};

            #pragma unroll
            for (int ss = 0; ss < 2; ss++) {
                #pragma unroll
                for (int t = 0; t < 4; t++) {
                    int L = k * 4 + t;
                    float ca = c[8 * ss + t];
                    float cb = c[8 * ss + t + 4];
                    float cah = tf32_rn(ca), cal = tf32_rn(ca - cah);
                    float cbh = tf32_rn(cb), cbl = tf32_rn(cb - cbh);
                    g_Bf[m][ss * 2 + 0][L][0] = cah;
                    g_Bf[m][ss * 2 + 1][L][0] = cal;
                    g_Bf[m][ss * 2 + 0][L][1] = cbh;
                    g_Bf[m][ss * 2 + 1][L][1] = cbl;
                }
            }

            g_zT[k * 4 + 0][m] = mu0;
            g_zT[k * 4 + 1][m] = mu1;
            g_zT[k * 4 + 2][m] = mu2;
            g_zT[k * 4 + 3][m] = mu3;
            g_zT[32 + k * 4 + 0][m] = __logf(fmaxf(fabsf(L00), 1e-6f));
            g_zT[32 + k * 4 + 1][m] = __logf(fmaxf(fabsf(L11), 1e-6f));
            g_zT[32 + k * 4 + 2][m] = __logf(fmaxf(fabsf(L22), 1e-6f));
            g_zT[32 + k * 4 + 3][m] = __logf(fmaxf(fabsf(L33), 1e-6f));
            g_zT[64 + k][m] = pik;
        } else if (gid < M_ROWS * K_COMP + B_PTS) {
            const int p = gid - M_ROWS * K_COMP;
            float4 xv = X[p];
            float f[16] = {xv.x*xv.x, xv.y*xv.y, xv.z*xv.z, xv.w*xv.w,
                           xv.x*xv.y, xv.x*xv.z, xv.x*xv.w,
                           xv.y*xv.z, xv.y*xv.w, xv.z*xv.w,
                           xv.x, xv.y, xv.z, xv.w, 1.0f, 0.0f};
            const int T = p >> 4;
            const int row = p & 15;
            const int gg = row & 7;
            const bool up = row < 8;
            const int rA = up ? 0 : 1;
            const int rB = up ? 2 : 3;
            #pragma unroll
            for (int ss = 0; ss < 2; ss++) {
                #pragma unroll
                for (int t = 0; t < 4; t++) {
                    int L = gg * 4 + t;
                    float fa = f[8 * ss + t];
                    float fb = f[8 * ss + t + 4];
                    float fah = tf32_rn(fa), fal = tf32_rn(fa - fah);
                    float fbh = tf32_rn(fb), fbl = tf32_rn(fb - fbh);
                    g_Af[T][ss][0][L][rA] = fah;
                    g_Af[T][ss][1][L][rA] = fal;
                    g_Af[T][ss][0][L][rB] = fbh;
                    g_Af[T][ss][1][L][rB] = fbl;
                }
            }
        }
    }

    grid_barrier(&g_bar[0]);

    // ================= PHASE 1: warp tickets (m, 256-pt chunk = 16 tiles) ====
    for (;;) {
        unsigned t;
        if (lane == 0) t = atomicAdd(&g_ticket, 1u);
        t = __shfl_sync(0xffffffffu, t, 0);
        if (t >= NTICK) break;
        const int ch = t >> 9;          // chunk (A frags shared by 512 consecutive tickets)
        const int m = t & 511;

        // B frags for this m (hi/lo x 2 ksteps)
        const float2* bp = (const float2*)&g_Bf[m][0][0][0];
        float2 bf0 = bp[0 * 32 + lane];
        float2 bf1 = bp[1 * 32 + lane];
        float2 bf2 = bp[2 * 32 + lane];
        float2 bf3 = bp[3 * 32 + lane];
        uint32_t b0x = __float_as_uint(bf0.x), b0y = __float_as_uint(bf0.y);
        uint32_t b1x = __float_as_uint(bf1.x), b1y = __float_as_uint(bf1.y);
        uint32_t b2x = __float_as_uint(bf2.x), b2y = __float_as_uint(bf2.y);
        uint32_t b3x = __float_as_uint(bf3.x), b3y = __float_as_uint(bf3.y);

        float acc[K_COMP];
        #pragma unroll
        for (int k = 0; k < K_COMP; k++) acc[k] = 0.f;

        const int r = lane >> 2, tt = lane & 3;     // D frag coords
        const int eu = lane >> 4, erow = lane & 15; // epilogue coords

        #pragma unroll 2
        for (int tp = 0; tp < 8; tp++) {
            const int T0 = ch * 16 + tp * 2;        // 16 tiles per chunk
            #pragma unroll
            for (int u = 0; u < 2; u++) {
                const uint4* ap = (const uint4*)&g_Af[T0 + u][0][0][0][0];
                uint4 a0 = ap[0 * 32 + lane];
                uint4 a1 = ap[1 * 32 + lane];
                uint4 a2 = ap[2 * 32 + lane];
                uint4 a3 = ap[3 * 32 + lane];

                float d0 = 0.f, d1 = 0.f, d2 = 0.f, d3 = 0.f;
                mma_tf32(d0, d1, d2, d3, a0.x, a0.y, a0.z, a0.w, b0x, b0y);
                mma_tf32(d0, d1, d2, d3, a1.x, a1.y, a1.z, a1.w, b0x, b0y);
                mma_tf32(d0, d1, d2, d3, a0.x, a0.y, a0.z, a0.w, b1x, b1y);
                mma_tf32(d0, d1, d2, d3, a2.x, a2.y, a2.z, a2.w, b2x, b2y);
                mma_tf32(d0, d1, d2, d3, a3.x, a3.y, a3.z, a3.w, b2x, b2y);
                mma_tf32(d0, d1, d2, d3, a2.x, a2.y, a2.z, a2.w, b3x, b3y);

                *(float2*)&sD[wid][u][r][2 * tt] = make_float2(d0, d1);
                *(float2*)&sD[wid][u][r + 8][2 * tt] = make_float2(d2, d3);
            }
            __syncwarp();

            // epilogue: each lane owns one point (tile eu, row erow)
            const float* qrow = &sD[wid][eu][erow][0];
            float4 qa = *(const float4*)qrow;
            float4 qb = *(const float4*)(qrow + 4);
            float mn = fminf(fminf(fminf(qa.x, qa.y), fminf(qa.z, qa.w)),
                             fminf(fminf(qb.x, qb.y), fminf(qb.z, qb.w)));
            float e0 = ex2f(mn - qa.x);
            float e1 = ex2f(mn - qa.y);
            float e2 = ex2f(mn - qa.z);
            float e3 = ex2f(mn - qa.w);
            float e4 = ex2f(mn - qb.x);
            float e5 = ex2f(mn - qb.y);
            float e6 = ex2f(mn - qb.z);
            float e7 = ex2f(mn - qb.w);
            float s = ((e0 + e1) + (e2 + e3)) + ((e4 + e5) + (e6 + e7));
            float inv = rcpf(s);            // s >= 1
            acc[0] = __fmaf_rn(e0, inv, acc[0]);
            acc[1] = __fmaf_rn(e1, inv, acc[1]);
            acc[2] = __fmaf_rn(e2, inv, acc[2]);
            acc[3] = __fmaf_rn(e3, inv, acc[3]);
            acc[4] = __fmaf_rn(e4, inv, acc[4]);
            acc[5] = __fmaf_rn(e5, inv, acc[5]);
            acc[6] = __fmaf_rn(e6, inv, acc[6]);
            acc[7] = __fmaf_rn(e7, inv, acc[7]);
            __syncwarp();   // protect sD before next tile-pair
        }

        // once-per-ticket reduction over 32 lanes
        #pragma unroll
        for (int k = 0; k < K_COMP; k++) {
            float v = acc[k];
            v += __shfl_xor_sync(0xffffffffu, v, 16);
            v += __shfl_xor_sync(0xffffffffu, v, 8);
            v += __shfl_xor_sync(0xffffffffu, v, 4);
            v += __shfl_xor_sync(0xffffffffu, v, 2);
            v += __shfl_xor_sync(0xffffffffu, v, 1);
            acc[k] = v;
        }
        if (lane == 0) {
            #pragma unroll
            for (int k = 0; k < K_COMP; k++) g_respC[ch][k][m] = acc[k];
        }
    }

    grid_barrier(&g_bar[1]);

    // ================= PHASE 1.5: reduce chunk partials ======================
    {
        int gid = blockIdx.x * 256 + tid;
        if (gid < K_COMP * M_ROWS) {
            const int k = gid >> 9, m = gid & 511;
            float s = 0.f;
            #pragma unroll
            for (int ch = 0; ch < CH_N; ch++) s += g_respC[ch][k][m];
            g_respF[k][m] = s * (1.0f / (float)B_PTS);
        }
    }

    grid_barrier(&g_bar[2]);

    // ================= PHASE 2: standardization (blocks 0..79) ===============
    if (blockIdx.x < Z_COLS) {
        const int c = blockIdx.x;
        float v[2];
        if (c < 72) {
            const float* col = g_zT[c];
            #pragma unroll
            for (int j = 0; j < 2; j++) v[j] = col[tid + 256 * j];
        } else {
            const float* col = g_respF[c - 72];
            #pragma unroll
            for (int j = 0; j < 2; j++) v[j] = col[tid + 256 * j];
        }

        __shared__ float nsh[8];
        __shared__ float n_mean, n_rstd;

        float s = v[0] + v[1];
        s += __shfl_down_sync(0xffffffffu, s, 16);
        s += __shfl_down_sync(0xffffffffu, s, 8);
        s += __shfl_down_sync(0xffffffffu, s, 4);
        s += __shfl_down_sync(0xffffffffu, s, 2);
        s += __shfl_down_sync(0xffffffffu, s, 1);
        if (lane == 0) nsh[wid] = s;
        __syncthreads();
        if (tid == 0) {
            float t2 = ((nsh[0] + nsh[1]) + (nsh[2] + nsh[3])) +
                       ((nsh[4] + nsh[5]) + (nsh[6] + nsh[7]));
            n_mean = t2 * (1.0f / (float)M_ROWS);
        }
        __syncthreads();
        float mean = n_mean;

        float qsum = 0.f;
        #pragma unroll
        for (int j = 0; j < 2; j++) {
            v[j] -= mean;
            qsum = __fmaf_rn(v[j], v[j], qsum);
        }
        qsum += __shfl_down_sync(0xffffffffu, qsum, 16);
        qsum += __shfl_down_sync(0xffffffffu, qsum, 8);
        qsum += __shfl_down_sync(0xffffffffu, qsum, 4);
        qsum += __shfl_down_sync(0xffffffffu, qsum, 2);
        qsum += __shfl_down_sync(0xffffffffu, qsum, 1);
        __syncthreads();
        if (lane == 0) nsh[wid] = qsum;
        __syncthreads();
        if (tid == 0) {
            float t2 = ((nsh[0] + nsh[1]) + (nsh[2] + nsh[3])) +
                       ((nsh[4] + nsh[5]) + (nsh[6] + nsh[7]));
            float var = t2 * (1.0f / (float)(M_ROWS - 1));
            n_rstd = 1.0f / fmaxf(sqrtf(var), 1e-6f);
        }
        __syncthreads();
        float rstd = n_rstd;
        #pragma unroll
        for (int j = 0; j < 2; j++) {
            int r2 = tid + 256 * j;
            out[r2 * Z_COLS + c] = v[j] * rstd;
        }
    }

    // ============== counter reset (state -> 0 for graph replay) ==============
    __syncthreads();
    if (tid == 0) {
        __threadfence();
        unsigned d = atomicAdd(&g_done, 1u);
        if (d == NBLK - 1) {
            g_ticket = 0u;
            g_bar[0] = 0u;
            g_bar[1] = 0u;
            g_bar[2] = 0u;
            g_done = 0u;
            __threadfence();
        }
    }
}

// ---------------------------------------------------------------------------
extern "C" void kernel_launch(void* const* d_in, const int* in_sizes, int n_in,
                              void* d_out, int out_size) {
    const float* phi = (const float*)d_in[0];
    const float4* X = (const float4*)d_in[1];
    float* out = (float*)d_out;

    gmm_all<<<NBLK, 256>>>(phi, X, out);
}

// round 12
// speedup vs baseline: 1.3211x; 1.0009x over previous
#include <cuda_runtime.h>
#include <math.h>
#include <stdint.h>

#define M_ROWS 512
#define K_COMP 8
#define B_PTS  4096
#define PHI_DIM 120
#define Z_COLS 80
#define LOG2PI_F 1.8378770664093453f
#define LOG2E_F  1.4426950408889634f

#define NBLK   296          // 148 SMs x 2 CTAs x 256 threads
#define NTILE  256          // 4096 pts / 16 per mma tile
#define CH_N   16           // point-chunks of 256 points (16 tiles) per m
#define NTICK  (CH_N * M_ROWS)   // 8192 warp tickets

// Scratch (device globals — no allocation allowed)
__device__ float g_Af[NTILE][2][2][32][4];   // A (feature) frags: [tile][s][h][lane][reg]
__device__ float g_Bf[M_ROWS][4][32][2];     // B (coef) frags: [m][s*2+h][lane][reg]
__device__ float g_zT[72][M_ROWS];           // z cols 0..71, column-major
__device__ float g_respC[CH_N][K_COMP][M_ROWS];  // per-chunk resp partials
__device__ float g_respF[K_COMP][M_ROWS];    // reduced resp
__device__ unsigned g_ticket, g_bar[3], g_done;

__device__ __forceinline__ float ex2f(float x) {
    float r; asm("ex2.approx.f32 %0, %1;" : "=f"(r) : "f"(x)); return r;
}
__device__ __forceinline__ float rcpf(float x) {
    float r; asm("rcp.approx.f32 %0, %1;" : "=f"(r) : "f"(x)); return r;
}
__device__ __forceinline__ float tf32_rn(float v) {
    uint32_t u; asm("cvt.rna.tf32.f32 %0, %1;" : "=r"(u) : "f"(v));
    return __uint_as_float(u);
}
__device__ __forceinline__ void mma_tf32(float& d0, float& d1, float& d2, float& d3,
                                         uint32_t a0, uint32_t a1, uint32_t a2, uint32_t a3,
                                         uint32_t b0, uint32_t b1) {
    asm volatile("mma.sync.aligned.m16n8k8.row.col.f32.tf32.tf32.f32 "
                 "{%0,%1,%2,%3}, {%4,%5,%6,%7}, {%8,%9}, {%0,%1,%2,%3};"
                 : "+f"(d0), "+f"(d1), "+f"(d2), "+f"(d3)
                 : "r"(a0), "r"(a1), "r"(a2), "r"(a3), "r"(b0), "r"(b1));
}

__device__ __forceinline__ void grid_barrier(unsigned* ctr) {
    __syncthreads();
    if (threadIdx.x == 0) {
        __threadfence();
        atomicAdd(ctr, 1u);
        volatile unsigned* p = ctr;
        while (*p < NBLK) __nanosleep(64);
    }
    __syncthreads();
    __threadfence();
}

// ---------------------------------------------------------------------------
__global__ void __launch_bounds__(256, 2) gmm_all(const float* __restrict__ phi,
                                                  const float4* __restrict__ X,
                                                  float* __restrict__ out) {
    const int tid = threadIdx.x;
    const unsigned lane = tid & 31;
    const unsigned wid = tid >> 5;

    // per-warp D staging, double-buffered: [warp][buf][tile-in-pair][row][stride12]
    __shared__ __align__(16) float sD[8][2][2][16][12];

    // ================= PHASE 0: prep (coef tasks 0..4095, feature 4096..8191)
    {
        int gid = blockIdx.x * 256 + tid;
        if (gid < M_ROWS * K_COMP) {
            const int m = gid >> 3, k = gid & 7;
            const float* pm = phi + m * PHI_DIM;

            float mx = -INFINITY;
            #pragma unroll
            for (int j = 0; j < K_COMP; j++) mx = fmaxf(mx, pm[j]);
            float s = 0.f;
            #pragma unroll
            for (int j = 0; j < K_COMP; j++) s += __expf(pm[j] - mx);
            float pik = __expf(pm[k] - mx) / s;

            float mu0 = pm[8 + k * 4 + 0];
            float mu1 = pm[8 + k * 4 + 1];
            float mu2 = pm[8 + k * 4 + 2];
            float mu3 = pm[8 + k * 4 + 3];

            const float* lv = pm + 40 + k * 10;
            float L00 = lv[0], L10 = lv[1], L11 = lv[2], L20 = lv[3], L21 = lv[4];
            float L22 = lv[5], L30 = lv[6], L31 = lv[7], L32 = lv[8], L33 = lv[9];

            float G00 = 1.0f / L00, G11 = 1.0f / L11, G22 = 1.0f / L22, G33 = 1.0f / L33;
            float G10 = -L10 * G00 * G11;
            float G21 = -L21 * G11 * G22;
            float G20 = -(L20 * G00 + L21 * G10) * G22;
            float G32 = -L32 * G22 * G33;
            float G31 = -(L31 * G11 + L32 * G21) * G33;
            float G30 = -(L30 * G00 + L31 * G10 + L32 * G20) * G33;

            const float sc = sqrtf(0.5f * LOG2E_F);
            float A00 = sc * G00, A10 = sc * G10, A11 = sc * G11;
            float A20 = sc * G20, A21 = sc * G21, A22 = sc * G22;
            float A30 = sc * G30, A31 = sc * G31, A32 = sc * G32, A33 = sc * G33;

            float B0 = -(A00 * mu0);
            float B1 = -(A10 * mu0 + A11 * mu1);
            float B2 = -(A20 * mu0 + A21 * mu1 + A22 * mu2);
            float B3 = -(A30 * mu0 + A31 * mu1 + A32 * mu2 + A33 * mu3);

            float log_det = 2.0f * (__logf(fmaxf(fabsf(L00), 1e-8f)) +
                                    __logf(fmaxf(fabsf(L11), 1e-8f)) +
                                    __logf(fmaxf(fabsf(L22), 1e-8f)) +
                                    __logf(fmaxf(fabsf(L33), 1e-8f)));
            float ckv = __logf(fmaxf(pik, 1e-8f)) - 0.5f * (4.0f * LOG2PI_F + log_det);
            float ck2 = ckv * LOG2E_F;

            float S00 = A00*A00 + A10*A10 + A20*A20 + A30*A30;
            float S01 = A10*A11 + A20*A21 + A30*A31;
            float S02 = A20*A22 + A30*A32;
            float S03 = A30*A33;
            float S11 = A11*A11 + A21*A21 + A31*A31;
            float S12 = A21*A22 + A31*A32;
            float S13 = A31*A33;
            float S22 = A22*A22 + A32*A32;
            float S23 = A32*A33;
            float S33 = A33*A33;
            float w0 = A00*B0 + A10*B1 + A20*B2 + A30*B3;
            float w1 = A11*B1 + A21*B2 + A31*B3;
            float w2 = A22*B2 + A32*B3;
            float w3 = A33*B3;
            float cc = B0*B0 + B1*B1 + B2*B2 + B3*B3 - ck2;

            float c[16] = {S00, S11, S22, S33,
                           2.f*S01, 2.f*S02, 2.f*S03, 2.f*S12, 2.f*S13, 2.f*S23,
                           2.f*w0, 2.f*w1, 2.f*w2, 2.f*w3, cc, 0.f};

            #pragma unroll
            for (int ss = 0; ss < 2; ss++) {
                #pragma unroll
                for (int t = 0; t < 4; t++) {
                    int L = k * 4 + t;
                    float ca = c[8 * ss + t];
                    float cb = c[8 * ss + t + 4];
                    float cah = tf32_rn(ca), cal = tf32_rn(ca - cah);
                    float cbh = tf32_rn(cb), cbl = tf32_rn(cb - cbh);
                    g_Bf[m][ss * 2 + 0][L][0] = cah;
                    g_Bf[m][ss * 2 + 1][L][0] = cal;
                    g_Bf[m][ss * 2 + 0][L][1] = cbh;
                    g_Bf[m][ss * 2 + 1][L][1] = cbl;
                }
            }

            g_zT[k * 4 + 0][m] = mu0;
            g_zT[k * 4 + 1][m] = mu1;
            g_zT[k * 4 + 2][m] = mu2;
            g_zT[k * 4 + 3][m] = mu3;
            g_zT[32 + k * 4 + 0][m] = __logf(fmaxf(fabsf(L00), 1e-6f));
            g_zT[32 + k * 4 + 1][m] = __logf(fmaxf(fabsf(L11), 1e-6f));
            g_zT[32 + k * 4 + 2][m] = __logf(fmaxf(fabsf(L22), 1e-6f));
            g_zT[32 + k * 4 + 3][m] = __logf(fmaxf(fabsf(L33), 1e-6f));
            g_zT[64 + k][m] = pik;
        } else if (gid < M_ROWS * K_COMP + B_PTS) {
            const int p = gid - M_ROWS * K_COMP;
            float4 xv = X[p];
            float f[16] = {xv.x*xv.x, xv.y*xv.y, xv.z*xv.z, xv.w*xv.w,
                           xv.x*xv.y, xv.x*xv.z, xv.x*xv.w,
                           xv.y*xv.z, xv.y*xv.w, xv.z*xv.w,
                           xv.x, xv.y, xv.z, xv.w, 1.0f, 0.0f};
            const int T = p >> 4;
            const int row = p & 15;
            const int gg = row & 7;
            const bool up = row < 8;
            const int rA = up ? 0 : 1;
            const int rB = up ? 2 : 3;
            #pragma unroll
            for (int ss = 0; ss < 2; ss++) {
                #pragma unroll
                for (int t = 0; t < 4; t++) {
                    int L = gg * 4 + t;
                    float fa = f[8 * ss + t];
                    float fb = f[8 * ss + t + 4];
                    float fah = tf32_rn(fa), fal = tf32_rn(fa - fah);
                    float fbh = tf32_rn(fb), fbl = tf32_rn(fb - fbh);
                    g_Af[T][ss][0][L][rA] = fah;
                    g_Af[T][ss][1][L][rA] = fal;
                    g_Af[T][ss][0][L][rB] = fbh;
                    g_Af[T][ss][1][L][rB] = fbl;
                }
            }
        }
    }

    grid_barrier(&g_bar[0]);

    // ================= PHASE 1: warp tickets (m, 256-pt chunk = 16 tiles) ====
    for (;;) {
        unsigned t;
        if (lane == 0) t = atomicAdd(&g_ticket, 1u);
        t = __shfl_sync(0xffffffffu, t, 0);
        if (t >= NTICK) break;
        const int ch = t >> 9;
        const int m = t & 511;

        // B frags for this m (hi/lo x 2 ksteps)
        const float2* bp = (const float2*)&g_Bf[m][0][0][0];
        float2 bf0 = bp[0 * 32 + lane];
        float2 bf1 = bp[1 * 32 + lane];
        float2 bf2 = bp[2 * 32 + lane];
        float2 bf3 = bp[3 * 32 + lane];
        uint32_t b0x = __float_as_uint(bf0.x), b0y = __float_as_uint(bf0.y);
        uint32_t b1x = __float_as_uint(bf1.x), b1y = __float_as_uint(bf1.y);
        uint32_t b2x = __float_as_uint(bf2.x), b2y = __float_as_uint(bf2.y);
        uint32_t b3x = __float_as_uint(bf3.x), b3y = __float_as_uint(bf3.y);

        float acc[K_COMP];
        #pragma unroll
        for (int k = 0; k < K_COMP; k++) acc[k] = 0.f;

        const int r = lane >> 2, tt = lane & 3;     // D frag coords
        const int eu = lane >> 4, erow = lane & 15; // epilogue coords

        // A-frag base for this chunk: tile stride = 128 uint4
        const uint4* apc = (const uint4*)&g_Af[ch * 16][0][0][0][0];

        // preload tile-pair 0
        uint4 A[2][4];
        #pragma unroll
        for (int u = 0; u < 2; u++)
            #pragma unroll
            for (int j = 0; j < 4; j++)
                A[u][j] = apc[u * 128 + j * 32 + lane];

        #pragma unroll
        for (int tp = 0; tp < 8; tp++) {
            // prefetch tile-pair tp+1 (hidden under mma + epilogue)
            uint4 N[2][4];
            if (tp < 7) {
                const uint4* apn = apc + (tp + 1) * 256;
                #pragma unroll
                for (int u = 0; u < 2; u++)
                    #pragma unroll
                    for (int j = 0; j < 4; j++)
                        N[u][j] = apn[u * 128 + j * 32 + lane];
            }

            const int buf = tp & 1;
            #pragma unroll
            for (int u = 0; u < 2; u++) {
                float d0 = 0.f, d1 = 0.f, d2 = 0.f, d3 = 0.f;
                mma_tf32(d0, d1, d2, d3, A[u][0].x, A[u][0].y, A[u][0].z, A[u][0].w, b0x, b0y);
                mma_tf32(d0, d1, d2, d3, A[u][1].x, A[u][1].y, A[u][1].z, A[u][1].w, b0x, b0y);
                mma_tf32(d0, d1, d2, d3, A[u][0].x, A[u][0].y, A[u][0].z, A[u][0].w, b1x, b1y);
                mma_tf32(d0, d1, d2, d3, A[u][2].x, A[u][2].y, A[u][2].z, A[u][2].w, b2x, b2y);
                mma_tf32(d0, d1, d2, d3, A[u][3].x, A[u][3].y, A[u][3].z, A[u][3].w, b2x, b2y);
                mma_tf32(d0, d1, d2, d3, A[u][2].x, A[u][2].y, A[u][2].z, A[u][2].w, b3x, b3y);

                *(float2*)&sD[wid][buf][u][r][2 * tt] = make_float2(d0, d1);
                *(float2*)&sD[wid][buf][u][r + 8][2 * tt] = make_float2(d2, d3);
            }
            __syncwarp();

            // epilogue: each lane owns one point (tile eu, row erow)
            const float* qrow = &sD[wid][buf][eu][erow][0];
            float4 qa = *(const float4*)qrow;
            float4 qb = *(const float4*)(qrow + 4);
            float mn = fminf(fminf(fminf(qa.x, qa.y), fminf(qa.z, qa.w)),
                             fminf(fminf(qb.x, qb.y), fminf(qb.z, qb.w)));
            float e0 = ex2f(mn - qa.x);
            float e1 = ex2f(mn - qa.y);
            float e2 = ex2f(mn - qa.z);
            float e3 = ex2f(mn - qa.w);
            float e4 = ex2f(mn - qb.x);
            float e5 = ex2f(mn - qb.y);
            float e6 = ex2f(mn - qb.z);
            float e7 = ex2f(mn - qb.w);
            float s = ((e0 + e1) + (e2 + e3)) + ((e4 + e5) + (e6 + e7));
            float inv = rcpf(s);            // s >= 1
            acc[0] = __fmaf_rn(e0, inv, acc[0]);
            acc[1] = __fmaf_rn(e1, inv, acc[1]);
            acc[2] = __fmaf_rn(e2, inv, acc[2]);
            acc[3] = __fmaf_rn(e3, inv, acc[3]);
            acc[4] = __fmaf_rn(e4, inv, acc[4]);
            acc[5] = __fmaf_rn(e5, inv, acc[5]);
            acc[6] = __fmaf_rn(e6, inv, acc[6]);
            acc[7] = __fmaf_rn(e7, inv, acc[7]);
            // no trailing syncwarp: next round writes the other sD buffer

            if (tp < 7) {
                #pragma unroll
                for (int u = 0; u < 2; u++)
                    #pragma unroll
                    for (int j = 0; j < 4; j++)
                        A[u][j] = N[u][j];   // register rename under full unroll
            }
        }

        // once-per-ticket reduction over 32 lanes
        #pragma unroll
        for (int k = 0; k < K_COMP; k++) {
            float v = acc[k];
            v += __shfl_xor_sync(0xffffffffu, v, 16);
            v += __shfl_xor_sync(0xffffffffu, v, 8);
            v += __shfl_xor_sync(0xffffffffu, v, 4);
            v += __shfl_xor_sync(0xffffffffu, v, 2);
            v += __shfl_xor_sync(0xffffffffu, v, 1);
            acc[k] = v;
        }
        if (lane == 0) {
            #pragma unroll
            for (int k = 0; k < K_COMP; k++) g_respC[ch][k][m] = acc[k];
        }
    }

    grid_barrier(&g_bar[1]);

    // ================= PHASE 1.5: reduce chunk partials ======================
    {
        int gid = blockIdx.x * 256 + tid;
        if (gid < K_COMP * M_ROWS) {
            const int k = gid >> 9, m = gid & 511;
            float s = 0.f;
            #pragma unroll
            for (int ch = 0; ch < CH_N; ch++) s += g_respC[ch][k][m];
            g_respF[k][m] = s * (1.0f / (float)B_PTS);
        }
    }

    grid_barrier(&g_bar[2]);

    // ================= PHASE 2: standardization (blocks 0..79) ===============
    if (blockIdx.x < Z_COLS) {
        const int c = blockIdx.x;
        float v[2];
        if (c < 72) {
            const float* col = g_zT[c];
            #pragma unroll
            for (int j = 0; j < 2; j++) v[j] = col[tid + 256 * j];
        } else {
            const float* col = g_respF[c - 72];
            #pragma unroll
            for (int j = 0; j < 2; j++) v[j] = col[tid + 256 * j];
        }

        __shared__ float nsh[8];
        __shared__ float n_mean, n_rstd;

        float s = v[0] + v[1];
        s += __shfl_down_sync(0xffffffffu, s, 16);
        s += __shfl_down_sync(0xffffffffu, s, 8);
        s += __shfl_down_sync(0xffffffffu, s, 4);
        s += __shfl_down_sync(0xffffffffu, s, 2);
        s += __shfl_down_sync(0xffffffffu, s, 1);
        if (lane == 0) nsh[wid] = s;
        __syncthreads();
        if (tid == 0) {
            float t2 = ((nsh[0] + nsh[1]) + (nsh[2] + nsh[3])) +
                       ((nsh[4] + nsh[5]) + (nsh[6] + nsh[7]));
            n_mean = t2 * (1.0f / (float)M_ROWS);
        }
        __syncthreads();
        float mean = n_mean;

        float qsum = 0.f;
        #pragma unroll
        for (int j = 0; j < 2; j++) {
            v[j] -= mean;
            qsum = __fmaf_rn(v[j], v[j], qsum);
        }
        qsum += __shfl_down_sync(0xffffffffu, qsum, 16);
        qsum += __shfl_down_sync(0xffffffffu, qsum, 8);
        qsum += __shfl_down_sync(0xffffffffu, qsum, 4);
        qsum += __shfl_down_sync(0xffffffffu, qsum, 2);
        qsum += __shfl_down_sync(0xffffffffu, qsum, 1);
        __syncthreads();
        if (lane == 0) nsh[wid] = qsum;
        __syncthreads();
        if (tid == 0) {
            float t2 = ((nsh[0] + nsh[1]) + (nsh[2] + nsh[3])) +
                       ((nsh[4] + nsh[5]) + (nsh[6] + nsh[7]));
            float var = t2 * (1.0f / (float)(M_ROWS - 1));
            n_rstd = 1.0f / fmaxf(sqrtf(var), 1e-6f);
        }
        __syncthreads();
        float rstd = n_rstd;
        #pragma unroll
        for (int j = 0; j < 2; j++) {
            int r2 = tid + 256 * j;
            out[r2 * Z_COLS + c] = v[j] * rstd;
        }
    }

    // ============== counter reset (state -> 0 for graph replay) ==============
    __syncthreads();
    if (tid == 0) {
        __threadfence();
        unsigned d = atomicAdd(&g_done, 1u);
        if (d == NBLK - 1) {
            g_ticket = 0u;
            g_bar[0] = 0u;
            g_bar[1] = 0u;
            g_bar[2] = 0u;
            g_done = 0u;
            __threadfence();
        }
    }
}

// ---------------------------------------------------------------------------
extern "C" void kernel_launch(void* const* d_in, const int* in_sizes, int n_in,
                              void* d_out, int out_size) {
    const float* phi = (const float*)d_in[0];
    const float4* X = (const float4*)d_in[1];
    float* out = (float*)d_out;

    gmm_all<<<NBLK, 256>>>(phi, X, out);
}

// round 13
// speedup vs baseline: 1.7645x; 1.3356x over previous
#include <cuda_runtime.h>
#include <math.h>

#define M_ROWS 512
#define K_COMP 8
#define B_PTS  4096
#define B_QTR  1024
#define PHI_DIM 120
#define Z_COLS 80
#define LOG2PI_F 1.8378770664093453f
#define LOG2E_F  1.4426950408889634f

#define NBLK   444              // 148 SMs x 3 CTAs, residency via launch_bounds
#define NITEM  2048             // 512 m x 4 quarters

// Scratch (device globals — no allocation allowed)
__device__ float g_zT[72][M_ROWS];            // z cols 0..71, column-major
__device__ float g_respT[4][K_COMP][M_ROWS];  // per-quarter resp partials
__device__ unsigned g_arrive, g_done;

__device__ __forceinline__ float ex2f(float x) {
    float r; asm("ex2.approx.f32 %0, %1;" : "=f"(r) : "f"(x)); return r;
}
__device__ __forceinline__ float rcpf(float x) {
    float r; asm("rcp.approx.f32 %0, %1;" : "=f"(r) : "f"(x)); return r;
}

// ---------------------------------------------------------------------------
// One persistent kernel: static-stride (m,quarter) items -> grid barrier -> norm.
// ---------------------------------------------------------------------------
__global__ void __launch_bounds__(128, 3) gmm_all(const float* __restrict__ phi,
                                                  const float4* __restrict__ X,
                                                  float* __restrict__ out) {
    const int tid = threadIdx.x;
    const unsigned lane = tid & 31;
    const unsigned wid = tid >> 5;

    // Per k: A (lower-tri, 10), b0..b3, nck2 (= -ck*log2e)
    __shared__ float sp[K_COMP][15];
    __shared__ float sred[4][K_COMP];

    // ===================== PHASE 1: static-stride items ======================
    // 444 % 4 == 0  =>  each block keeps the same X-quarter (L1-resident).
    for (int item = blockIdx.x; item < NITEM; item += NBLK) {
        const int m = item >> 2;
        const int q = item & 3;

        // ---- prep: threads 0..7, one k each ----
        if (tid < K_COMP) {
            const int k = tid;
            const float* pm = phi + m * PHI_DIM;

            float mx = -INFINITY;
            #pragma unroll
            for (int j = 0; j < K_COMP; j++) mx = fmaxf(mx, pm[j]);
            float s = 0.f;
            #pragma unroll
            for (int j = 0; j < K_COMP; j++) s += __expf(pm[j] - mx);
            float pik = __expf(pm[k] - mx) / s;

            float mu0 = pm[8 + k * 4 + 0];
            float mu1 = pm[8 + k * 4 + 1];
            float mu2 = pm[8 + k * 4 + 2];
            float mu3 = pm[8 + k * 4 + 3];

            const float* lv = pm + 40 + k * 10;
            float L00 = lv[0], L10 = lv[1], L11 = lv[2], L20 = lv[3], L21 = lv[4];
            float L22 = lv[5], L30 = lv[6], L31 = lv[7], L32 = lv[8], L33 = lv[9];

            float G00 = 1.0f / L00, G11 = 1.0f / L11, G22 = 1.0f / L22, G33 = 1.0f / L33;
            float G10 = -L10 * G00 * G11;
            float G21 = -L21 * G11 * G22;
            float G20 = -(L20 * G00 + L21 * G10) * G22;
            float G32 = -L32 * G22 * G33;
            float G31 = -(L31 * G11 + L32 * G21) * G33;
            float G30 = -(L30 * G00 + L31 * G10 + L32 * G20) * G33;

            const float sc = sqrtf(0.5f * LOG2E_F);   // |a|^2 in log2 units
            float A00 = sc * G00, A10 = sc * G10, A11 = sc * G11;
            float A20 = sc * G20, A21 = sc * G21, A22 = sc * G22;
            float A30 = sc * G30, A31 = sc * G31, A32 = sc * G32, A33 = sc * G33;

            sp[k][0] = A00; sp[k][1] = A10; sp[k][2] = A11; sp[k][3] = A20;
            sp[k][4] = A21; sp[k][5] = A22; sp[k][6] = A30; sp[k][7] = A31;
            sp[k][8] = A32; sp[k][9] = A33;
            sp[k][10] = -(A00 * mu0);
            sp[k][11] = -(A10 * mu0 + A11 * mu1);
            sp[k][12] = -(A20 * mu0 + A21 * mu1 + A22 * mu2);
            sp[k][13] = -(A30 * mu0 + A31 * mu1 + A32 * mu2 + A33 * mu3);

            float log_det = 2.0f * (__logf(fmaxf(fabsf(L00), 1e-8f)) +
                                    __logf(fmaxf(fabsf(L11), 1e-8f)) +
                                    __logf(fmaxf(fabsf(L22), 1e-8f)) +
                                    __logf(fmaxf(fabsf(L33), 1e-8f)));
            float ckv = __logf(fmaxf(pik, 1e-8f)) - 0.5f * (4.0f * LOG2PI_F + log_det);
            sp[k][14] = -(ckv * LOG2E_F);             // nck2

            if (q == 0) {
                g_zT[k * 4 + 0][m] = mu0;
                g_zT[k * 4 + 1][m] = mu1;
                g_zT[k * 4 + 2][m] = mu2;
                g_zT[k * 4 + 3][m] = mu3;
                g_zT[32 + k * 4 + 0][m] = __logf(fmaxf(fabsf(L00), 1e-6f));
                g_zT[32 + k * 4 + 1][m] = __logf(fmaxf(fabsf(L11), 1e-6f));
                g_zT[32 + k * 4 + 2][m] = __logf(fmaxf(fabsf(L22), 1e-6f));
                g_zT[32 + k * 4 + 3][m] = __logf(fmaxf(fabsf(L33), 1e-6f));
                g_zT[64 + k][m] = pik;
            }
        }
        __syncthreads();

        // ---- cache params in registers (broadcast LDS) ----
        float A00[K_COMP], A10[K_COMP], A11[K_COMP], A20[K_COMP], A21[K_COMP];
        float A22[K_COMP], A30[K_COMP], A31[K_COMP], A32[K_COMP], A33[K_COMP];
        float b0[K_COMP], b1[K_COMP], b2[K_COMP], b3[K_COMP], nck[K_COMP];
        #pragma unroll
        for (int k = 0; k < K_COMP; k++) {
            A00[k] = sp[k][0]; A10[k] = sp[k][1]; A11[k] = sp[k][2];
            A20[k] = sp[k][3]; A21[k] = sp[k][4]; A22[k] = sp[k][5];
            A30[k] = sp[k][6]; A31[k] = sp[k][7]; A32[k] = sp[k][8]; A33[k] = sp[k][9];
            b0[k] = sp[k][10]; b1[k] = sp[k][11]; b2[k] = sp[k][12]; b3[k] = sp[k][13];
            nck[k] = sp[k][14];
        }

        float acc[K_COMP];
        #pragma unroll
        for (int k = 0; k < K_COMP; k++) acc[k] = 0.f;

        const int pbase = q * B_QTR + tid;
        #pragma unroll 2
        for (int it = 0; it < 8; it++) {
            float4 x = X[pbase + it * 128];
            float qv[K_COMP];
            #pragma unroll
            for (int k = 0; k < K_COMP; k++) {
                float a0 = __fmaf_rn(x.x, A00[k], b0[k]);
                float a1 = __fmaf_rn(x.x, A10[k], __fmaf_rn(x.y, A11[k], b1[k]));
                float a2 = __fmaf_rn(x.x, A20[k],
                           __fmaf_rn(x.y, A21[k], __fmaf_rn(x.z, A22[k], b2[k])));
                float a3 = __fmaf_rn(x.x, A30[k],
                           __fmaf_rn(x.y, A31[k],
                           __fmaf_rn(x.z, A32[k], __fmaf_rn(x.w, A33[k], b3[k]))));
                qv[k] = __fmaf_rn(a0, a0,
                        __fmaf_rn(a1, a1,
                        __fmaf_rn(a2, a2, __fmaf_rn(a3, a3, nck[k]))));
            }
            float mn = fminf(fminf(fminf(qv[0], qv[1]), fminf(qv[2], qv[3])),
                             fminf(fminf(qv[4], qv[5]), fminf(qv[6], qv[7])));
            float ex[K_COMP];
            #pragma unroll
            for (int k = 0; k < K_COMP; k++) ex[k] = ex2f(mn - qv[k]);
            float s = ((ex[0] + ex[1]) + (ex[2] + ex[3])) +
                      ((ex[4] + ex[5]) + (ex[6] + ex[7]));
            float inv = rcpf(s);                       // s >= 1, safe
            #pragma unroll
            for (int k = 0; k < K_COMP; k++) acc[k] = __fmaf_rn(ex[k], inv, acc[k]);
        }

        // ---- block reduce (4 warps) ----
        #pragma unroll
        for (int k = 0; k < K_COMP; k++) {
            float v = acc[k];
            v += __shfl_down_sync(0xffffffffu, v, 16);
            v += __shfl_down_sync(0xffffffffu, v, 8);
            v += __shfl_down_sync(0xffffffffu, v, 4);
            v += __shfl_down_sync(0xffffffffu, v, 2);
            v += __shfl_down_sync(0xffffffffu, v, 1);
            if (lane == 0) sred[wid][k] = v;
        }
        __syncthreads();
        if (tid < K_COMP) {
            g_respT[q][tid][m] = sred[0][tid] + sred[1][tid] +
                                 sred[2][tid] + sred[3][tid];
        }
        __syncthreads();   // protect sp/sred reuse next item
    }

    // ===================== grid barrier (all 444 resident) ====================
    __syncthreads();
    if (tid == 0) {
        __threadfence();
        atomicAdd(&g_arrive, 1u);
        volatile unsigned* p = &g_arrive;
        while (*p < NBLK) __nanosleep(64);
    }
    __syncthreads();
    __threadfence();

    // ===================== PHASE 2: standardization (blocks 0..79) ===========
    if (blockIdx.x < Z_COLS) {
        const int c = blockIdx.x;
        float v[4];
        if (c < 72) {
            const float* col = g_zT[c];
            #pragma unroll
            for (int j = 0; j < 4; j++) v[j] = col[tid + 128 * j];
        } else {
            const int k = c - 72;
            #pragma unroll
            for (int j = 0; j < 4; j++) {
                int r = tid + 128 * j;
                v[j] = (g_respT[0][k][r] + g_respT[1][k][r] +
                        g_respT[2][k][r] + g_respT[3][k][r]) * (1.0f / (float)B_PTS);
            }
        }

        __shared__ float nsh[4];
        __shared__ float n_mean, n_rstd;

        float s = (v[0] + v[1]) + (v[2] + v[3]);
        s += __shfl_down_sync(0xffffffffu, s, 16);
        s += __shfl_down_sync(0xffffffffu, s, 8);
        s += __shfl_down_sync(0xffffffffu, s, 4);
        s += __shfl_down_sync(0xffffffffu, s, 2);
        s += __shfl_down_sync(0xffffffffu, s, 1);
        if (lane == 0) nsh[wid] = s;
        __syncthreads();
        if (tid == 0) n_mean = (nsh[0] + nsh[1] + nsh[2] + nsh[3]) * (1.0f / (float)M_ROWS);
        __syncthreads();
        float mean = n_mean;

        float qsum = 0.f;
        #pragma unroll
        for (int j = 0; j < 4; j++) {
            v[j] -= mean;
            qsum = __fmaf_rn(v[j], v[j], qsum);
        }
        qsum += __shfl_down_sync(0xffffffffu, qsum, 16);
        qsum += __shfl_down_sync(0xffffffffu, qsum, 8);
        qsum += __shfl_down_sync(0xffffffffu, qsum, 4);
        qsum += __shfl_down_sync(0xffffffffu, qsum, 2);
        qsum += __shfl_down_sync(0xffffffffu, qsum, 1);
        __syncthreads();
        if (lane == 0) nsh[wid] = qsum;
        __syncthreads();
        if (tid == 0) {
            float var = (nsh[0] + nsh[1] + nsh[2] + nsh[3]) * (1.0f / (float)(M_ROWS - 1));
            n_rstd = 1.0f / fmaxf(sqrtf(var), 1e-6f);
        }
        __syncthreads();
        float rstd = n_rstd;
        #pragma unroll
        for (int j = 0; j < 4; j++) {
            int r = tid + 128 * j;
            out[r * Z_COLS + c] = v[j] * rstd;
        }
    }

    // ============== counter reset (state -> 0 for graph replay) ==============
    __syncthreads();
    if (tid == 0) {
        __threadfence();
        unsigned d = atomicAdd(&g_done, 1u);
        if (d == NBLK - 1) {
            g_arrive = 0u;
            g_done = 0u;
            __threadfence();
        }
    }
}

// ---------------------------------------------------------------------------
extern "C" void kernel_launch(void* const* d_in, const int* in_sizes, int n_in,
                              void* d_out, int out_size) {
    const float* phi = (const float*)d_in[0];
    const float4* X = (const float4*)d_in[1];
    float* out = (float*)d_out;

    gmm_all<<<NBLK, 128>>>(phi, X, out);
}